// round 1
// baseline (speedup 1.0000x reference)
#include <cuda_runtime.h>

#define D      128
#define DO2    256          // 2*D_OUT
#define NODES  50000
#define TILE   16           // nodes per block in gemm_ln (50000 % 16 == 0)
#define LN_EPS 1e-5f

// Scratch (no cudaMalloc allowed): aggregated neighbor features + transposed weights
__device__ float g_support[NODES * D];   // 25.6 MB
__device__ float g_Wt[D * DO2];          // Wt[k][c]: c<128 -> W_self[c][k], else W_neigh[c-128][k]

// ---------------------------------------------------------------------------
__global__ void zero_support_kernel() {
    int i = blockIdx.x * blockDim.x + threadIdx.x;
    const int n4 = NODES * D / 4;
    float4 z = make_float4(0.f, 0.f, 0.f, 0.f);
    if (i < n4) reinterpret_cast<float4*>(g_support)[i] = z;
}

// ---------------------------------------------------------------------------
__global__ void build_wt_kernel(const float* __restrict__ Ws,
                                const float* __restrict__ Wn) {
    int idx = blockIdx.x * blockDim.x + threadIdx.x;   // D*DO2 = 32768
    if (idx >= D * DO2) return;
    int k = idx / DO2;
    int c = idx % DO2;
    g_Wt[idx] = (c < D) ? Ws[c * D + k] : Wn[(c - D) * D + k];
}

// ---------------------------------------------------------------------------
// One warp per edge: lane l handles 4 consecutive features (float4).
// msgs = h[col] * val, scatter-add into g_support[row] via vector RED.
__global__ void spmm_scatter_kernel(const float* __restrict__ h,
                                    const int*  __restrict__ row,
                                    const int*  __restrict__ col,
                                    const float* __restrict__ val,
                                    int E) {
    int gw   = (blockIdx.x * blockDim.x + threadIdx.x) >> 5;
    int lane = threadIdx.x & 31;
    if (gw >= E) return;
    int   r = __ldg(row + gw);
    int   c = __ldg(col + gw);
    float v = __ldg(val + gw);

    float4 x = reinterpret_cast<const float4*>(h + (size_t)c * D)[lane];
    x.x *= v; x.y *= v; x.z *= v; x.w *= v;

    float4* dst = reinterpret_cast<float4*>(g_support + (size_t)r * D) + lane;
    atomicAdd(dst, x);   // sm_90+ vector red: one REDG.128 per lane
}

// ---------------------------------------------------------------------------
// Fused: self_h = h @ Ws^T + b_s ; neigh_h = support @ Wn^T + b_n ;
// x = relu(concat) ; LayerNorm(256) * gamma + beta -> out
// Block: 256 threads, 16 nodes. Thread layout: cq = tid&63 (4 channels),
// ng = tid>>6 (4 nodes). Register tile acc[4 nodes][4 channels].
__global__ __launch_bounds__(256)
void gemm_ln_kernel(const float* __restrict__ h,
                    const float* __restrict__ b_self,
                    const float* __restrict__ b_neigh,
                    const float* __restrict__ gamma,
                    const float* __restrict__ beta,
                    float* __restrict__ out) {
    __shared__ float sH[TILE][D];     // 8 KB
    __shared__ float sS[TILE][D];     // 8 KB
    __shared__ float sOut[TILE][DO2]; // 16 KB

    const int tid   = threadIdx.x;
    const int node0 = blockIdx.x * TILE;

    // Load node tiles (coalesced float4)
    {
        const float4* h4 = reinterpret_cast<const float4*>(h + (size_t)node0 * D);
        const float4* s4 = reinterpret_cast<const float4*>(g_support + (size_t)node0 * D);
        float4* sh4 = reinterpret_cast<float4*>(&sH[0][0]);
        float4* ss4 = reinterpret_cast<float4*>(&sS[0][0]);
        #pragma unroll
        for (int i = tid; i < TILE * D / 4; i += 256) {
            sh4[i] = h4[i];
            ss4[i] = s4[i];
        }
    }
    __syncthreads();

    const int cq = tid & 63;      // channel quad index: channels 4*cq .. 4*cq+3
    const int ng = tid >> 6;      // node group 0..3 -> nodes 4*ng .. 4*ng+3
    const int n0 = ng * 4;
    const bool neigh = (cq >= 32);
    const float (*sX)[D] = neigh ? sS : sH;

    float4 bias = neigh ? reinterpret_cast<const float4*>(b_neigh)[cq - 32]
                        : reinterpret_cast<const float4*>(b_self)[cq];

    float acc[4][4];
    #pragma unroll
    for (int j = 0; j < 4; j++) {
        acc[j][0] = bias.x; acc[j][1] = bias.y; acc[j][2] = bias.z; acc[j][3] = bias.w;
    }

    const float4* Wt4 = reinterpret_cast<const float4*>(g_Wt); // [k][64] float4s
    #pragma unroll 4
    for (int k = 0; k < D; k++) {
        float4 w = __ldg(Wt4 + k * 64 + cq);
        #pragma unroll
        for (int j = 0; j < 4; j++) {
            float xv = sX[n0 + j][k];   // warp-uniform -> LDS broadcast
            acc[j][0] = fmaf(w.x, xv, acc[j][0]);
            acc[j][1] = fmaf(w.y, xv, acc[j][1]);
            acc[j][2] = fmaf(w.z, xv, acc[j][2]);
            acc[j][3] = fmaf(w.w, xv, acc[j][3]);
        }
    }

    // ReLU + stage into shared for LN
    #pragma unroll
    for (int j = 0; j < 4; j++) {
        float4 r;
        r.x = fmaxf(acc[j][0], 0.f);
        r.y = fmaxf(acc[j][1], 0.f);
        r.z = fmaxf(acc[j][2], 0.f);
        r.w = fmaxf(acc[j][3], 0.f);
        reinterpret_cast<float4*>(&sOut[n0 + j][0])[cq] = r;
    }
    __syncthreads();

    // LayerNorm: 8 warps, 2 rows each; lane handles 8 values (2 float4)
    const int wid  = tid >> 5;
    const int lane = tid & 31;
    #pragma unroll
    for (int rr = 0; rr < 2; rr++) {
        int n = wid * 2 + rr;
        float4 a = reinterpret_cast<float4*>(&sOut[n][0])[lane];
        float4 b = reinterpret_cast<float4*>(&sOut[n][0])[lane + 32];
        float s  = a.x + a.y + a.z + a.w + b.x + b.y + b.z + b.w;
        float sq = a.x*a.x + a.y*a.y + a.z*a.z + a.w*a.w
                 + b.x*b.x + b.y*b.y + b.z*b.z + b.w*b.w;
        #pragma unroll
        for (int o = 16; o > 0; o >>= 1) {
            s  += __shfl_xor_sync(0xffffffffu, s,  o);
            sq += __shfl_xor_sync(0xffffffffu, sq, o);
        }
        float mu   = s * (1.f / 256.f);
        float var  = sq * (1.f / 256.f) - mu * mu;
        float rsig = rsqrtf(var + LN_EPS);

        float4 g1 = __ldg(reinterpret_cast<const float4*>(gamma) + lane);
        float4 g2 = __ldg(reinterpret_cast<const float4*>(gamma) + lane + 32);
        float4 e1 = __ldg(reinterpret_cast<const float4*>(beta)  + lane);
        float4 e2 = __ldg(reinterpret_cast<const float4*>(beta)  + lane + 32);

        float4 o1, o2;
        o1.x = (a.x - mu) * rsig * g1.x + e1.x;
        o1.y = (a.y - mu) * rsig * g1.y + e1.y;
        o1.z = (a.z - mu) * rsig * g1.z + e1.z;
        o1.w = (a.w - mu) * rsig * g1.w + e1.w;
        o2.x = (b.x - mu) * rsig * g2.x + e2.x;
        o2.y = (b.y - mu) * rsig * g2.y + e2.y;
        o2.z = (b.z - mu) * rsig * g2.z + e2.z;
        o2.w = (b.w - mu) * rsig * g2.w + e2.w;

        float4* og = reinterpret_cast<float4*>(out + (size_t)(node0 + n) * DO2);
        og[lane]      = o1;
        og[lane + 32] = o2;
    }
}

// ---------------------------------------------------------------------------
extern "C" void kernel_launch(void* const* d_in, const int* in_sizes, int n_in,
                              void* d_out, int out_size) {
    const float* h        = (const float*)d_in[0];
    const int*   edge_row = (const int*)  d_in[1];
    const int*   edge_col = (const int*)  d_in[2];
    const float* edge_val = (const float*)d_in[3];
    const float* W_self   = (const float*)d_in[4];
    const float* b_self   = (const float*)d_in[5];
    const float* W_neigh  = (const float*)d_in[6];
    const float* b_neigh  = (const float*)d_in[7];
    const float* ln_gamma = (const float*)d_in[8];
    const float* ln_beta  = (const float*)d_in[9];
    float*       out      = (float*)d_out;

    const int E = in_sizes[1];

    // 1) zero the scatter accumulator
    {
        int n4 = NODES * D / 4;
        zero_support_kernel<<<(n4 + 255) / 256, 256>>>();
    }
    // 2) build transposed/concatenated weight matrix
    build_wt_kernel<<<(D * DO2 + 255) / 256, 256>>>(W_self, W_neigh);

    // 3) SpMM scatter: one warp per edge
    {
        long long threads = (long long)E * 32;
        int blocks = (int)((threads + 255) / 256);
        spmm_scatter_kernel<<<blocks, 256>>>(h, edge_row, edge_col, edge_val, E);
    }
    // 4) fused GEMM + ReLU + LayerNorm
    gemm_ln_kernel<<<NODES / TILE, 256>>>(h, b_self, b_neigh, ln_gamma, ln_beta, out);
}

// round 2
// speedup vs baseline: 1.1498x; 1.1498x over previous
#include <cuda_runtime.h>

#define D      128
#define DO2    256          // 2*D_OUT
#define NODES  50000
#define TILE   32           // nodes per block in gemm_ln
#define LN_EPS 1e-5f

// Scratch (no cudaMalloc allowed)
__device__ float g_support[NODES * D];   // 25.6 MB
__device__ float g_Wt[D * DO2];          // Wt[k][c]

// ---------------------------------------------------------------------------
// Fused prep: zero the scatter accumulator + build transposed weight matrix.
__global__ void prep_kernel(const float* __restrict__ Ws,
                            const float* __restrict__ Wn) {
    int i = blockIdx.x * blockDim.x + threadIdx.x;
    const int n4 = NODES * D / 4;
    if (i < n4) {
        reinterpret_cast<float4*>(g_support)[i] = make_float4(0.f, 0.f, 0.f, 0.f);
    }
    if (i < D * DO2) {
        int k = i / DO2;
        int c = i % DO2;
        g_Wt[i] = (c < D) ? Ws[c * D + k] : Wn[(c - D) * D + k];
    }
}

// ---------------------------------------------------------------------------
// One warp per edge: lane l handles 4 consecutive features (float4).
__global__ void spmm_scatter_kernel(const float* __restrict__ h,
                                    const int*  __restrict__ row,
                                    const int*  __restrict__ col,
                                    const float* __restrict__ val,
                                    int E) {
    int gw   = (blockIdx.x * blockDim.x + threadIdx.x) >> 5;
    int lane = threadIdx.x & 31;
    if (gw >= E) return;
    int   r = __ldg(row + gw);
    int   c = __ldg(col + gw);
    float v = __ldg(val + gw);

    float4 x = reinterpret_cast<const float4*>(h + (size_t)c * D)[lane];
    x.x *= v; x.y *= v; x.z *= v; x.w *= v;

    float4* dst = reinterpret_cast<float4*>(g_support + (size_t)r * D) + lane;
    atomicAdd(dst, x);   // vector REDG.128
}

// ---------------------------------------------------------------------------
// Fused GEMM + concat + ReLU + LayerNorm.
// 256 threads, 32 nodes/block. cq = tid&63 (4 output channels),
// ng = tid>>6 (node group of 8). Register tile acc[8 nodes][4 channels].
// k-loop vectorized: LDS.128 loads 4 k-values per node row.
__global__ __launch_bounds__(256)
void gemm_ln_kernel(const float* __restrict__ h,
                    const float* __restrict__ b_self,
                    const float* __restrict__ b_neigh,
                    const float* __restrict__ gamma,
                    const float* __restrict__ beta,
                    float* __restrict__ out) {
    // 32 KB, reused: phase 1 = sH[32][128] + sS[32][128]; phase 2 = sOut[32][256]
    __shared__ float smem[TILE * DO2];
    float* sH = smem;
    float* sS = smem + TILE * D;

    const int tid   = threadIdx.x;
    const int node0 = blockIdx.x * TILE;

    // Load node tiles (coalesced float4), zero-pad past NODES
    for (int i = tid; i < TILE * (D / 4); i += 256) {
        int row   = i >> 5;           // D/4 = 32 float4 per row
        int gnode = node0 + row;
        float4 a = make_float4(0.f, 0.f, 0.f, 0.f);
        float4 s = a;
        if (gnode < NODES) {
            a = reinterpret_cast<const float4*>(h + (size_t)gnode * D)[i & 31];
            s = reinterpret_cast<const float4*>(g_support + (size_t)gnode * D)[i & 31];
        }
        reinterpret_cast<float4*>(sH)[i] = a;
        reinterpret_cast<float4*>(sS)[i] = s;
    }
    __syncthreads();

    const int  cq    = tid & 63;
    const int  ng    = tid >> 6;
    const int  n0    = ng * 8;
    const bool neigh = (cq >= 32);
    const float* sX  = neigh ? sS : sH;

    float4 bias = neigh ? reinterpret_cast<const float4*>(b_neigh)[cq - 32]
                        : reinterpret_cast<const float4*>(b_self)[cq];

    float acc[8][4];
    #pragma unroll
    for (int j = 0; j < 8; j++) {
        acc[j][0] = bias.x; acc[j][1] = bias.y; acc[j][2] = bias.z; acc[j][3] = bias.w;
    }

    const float4* Wt4 = reinterpret_cast<const float4*>(g_Wt); // [k][64]
    #pragma unroll 2
    for (int k = 0; k < D; k += 4) {
        float4 w0 = __ldg(Wt4 + (k + 0) * 64 + cq);
        float4 w1 = __ldg(Wt4 + (k + 1) * 64 + cq);
        float4 w2 = __ldg(Wt4 + (k + 2) * 64 + cq);
        float4 w3 = __ldg(Wt4 + (k + 3) * 64 + cq);
        #pragma unroll
        for (int j = 0; j < 8; j++) {
            float4 xv = *reinterpret_cast<const float4*>(sX + (n0 + j) * D + k);
            acc[j][0] = fmaf(w0.x, xv.x, acc[j][0]);
            acc[j][1] = fmaf(w0.y, xv.x, acc[j][1]);
            acc[j][2] = fmaf(w0.z, xv.x, acc[j][2]);
            acc[j][3] = fmaf(w0.w, xv.x, acc[j][3]);
            acc[j][0] = fmaf(w1.x, xv.y, acc[j][0]);
            acc[j][1] = fmaf(w1.y, xv.y, acc[j][1]);
            acc[j][2] = fmaf(w1.z, xv.y, acc[j][2]);
            acc[j][3] = fmaf(w1.w, xv.y, acc[j][3]);
            acc[j][0] = fmaf(w2.x, xv.z, acc[j][0]);
            acc[j][1] = fmaf(w2.y, xv.z, acc[j][1]);
            acc[j][2] = fmaf(w2.z, xv.z, acc[j][2]);
            acc[j][3] = fmaf(w2.w, xv.z, acc[j][3]);
            acc[j][0] = fmaf(w3.x, xv.w, acc[j][0]);
            acc[j][1] = fmaf(w3.y, xv.w, acc[j][1]);
            acc[j][2] = fmaf(w3.z, xv.w, acc[j][2]);
            acc[j][3] = fmaf(w3.w, xv.w, acc[j][3]);
        }
    }
    __syncthreads();   // all sX reads done; smem is now free to reuse

    // ReLU + stage into shared as sOut[32][256]
    #pragma unroll
    for (int j = 0; j < 8; j++) {
        float4 r;
        r.x = fmaxf(acc[j][0], 0.f);
        r.y = fmaxf(acc[j][1], 0.f);
        r.z = fmaxf(acc[j][2], 0.f);
        r.w = fmaxf(acc[j][3], 0.f);
        reinterpret_cast<float4*>(smem)[(n0 + j) * 64 + cq] = r;
    }
    __syncthreads();

    // LayerNorm: 8 warps, 4 rows each; lane handles 8 values (2 float4)
    const int wid  = tid >> 5;
    const int lane = tid & 31;

    float4 g1 = __ldg(reinterpret_cast<const float4*>(gamma) + lane);
    float4 g2 = __ldg(reinterpret_cast<const float4*>(gamma) + lane + 32);
    float4 e1 = __ldg(reinterpret_cast<const float4*>(beta)  + lane);
    float4 e2 = __ldg(reinterpret_cast<const float4*>(beta)  + lane + 32);

    #pragma unroll
    for (int rr = 0; rr < 4; rr++) {
        int n = wid * 4 + rr;
        float4 a = reinterpret_cast<float4*>(smem)[n * 64 + lane];
        float4 b = reinterpret_cast<float4*>(smem)[n * 64 + lane + 32];
        float s  = a.x + a.y + a.z + a.w + b.x + b.y + b.z + b.w;
        float sq = a.x*a.x + a.y*a.y + a.z*a.z + a.w*a.w
                 + b.x*b.x + b.y*b.y + b.z*b.z + b.w*b.w;
        #pragma unroll
        for (int o = 16; o > 0; o >>= 1) {
            s  += __shfl_xor_sync(0xffffffffu, s,  o);
            sq += __shfl_xor_sync(0xffffffffu, sq, o);
        }
        float mu   = s * (1.f / 256.f);
        float var  = sq * (1.f / 256.f) - mu * mu;
        float rsig = rsqrtf(var + LN_EPS);

        int gnode = node0 + n;
        if (gnode < NODES) {
            float4 o1, o2;
            o1.x = (a.x - mu) * rsig * g1.x + e1.x;
            o1.y = (a.y - mu) * rsig * g1.y + e1.y;
            o1.z = (a.z - mu) * rsig * g1.z + e1.z;
            o1.w = (a.w - mu) * rsig * g1.w + e1.w;
            o2.x = (b.x - mu) * rsig * g2.x + e2.x;
            o2.y = (b.y - mu) * rsig * g2.y + e2.y;
            o2.z = (b.z - mu) * rsig * g2.z + e2.z;
            o2.w = (b.w - mu) * rsig * g2.w + e2.w;

            float4* og = reinterpret_cast<float4*>(out + (size_t)gnode * DO2);
            og[lane]      = o1;
            og[lane + 32] = o2;
        }
    }
}

// ---------------------------------------------------------------------------
extern "C" void kernel_launch(void* const* d_in, const int* in_sizes, int n_in,
                              void* d_out, int out_size) {
    const float* h        = (const float*)d_in[0];
    const int*   edge_row = (const int*)  d_in[1];
    const int*   edge_col = (const int*)  d_in[2];
    const float* edge_val = (const float*)d_in[3];
    const float* W_self   = (const float*)d_in[4];
    const float* b_self   = (const float*)d_in[5];
    const float* W_neigh  = (const float*)d_in[6];
    const float* b_neigh  = (const float*)d_in[7];
    const float* ln_gamma = (const float*)d_in[8];
    const float* ln_beta  = (const float*)d_in[9];
    float*       out      = (float*)d_out;

    const int E = in_sizes[1];

    // 1) zero support + build Wt
    {
        int n4 = NODES * D / 4;
        prep_kernel<<<(n4 + 255) / 256, 256>>>(W_self, W_neigh);
    }
    // 2) SpMM scatter: one warp per edge
    {
        long long threads = (long long)E * 32;
        int blocks = (int)((threads + 255) / 256);
        spmm_scatter_kernel<<<blocks, 256>>>(h, edge_row, edge_col, edge_val, E);
    }
    // 3) fused GEMM + ReLU + LayerNorm
    gemm_ln_kernel<<<(NODES + TILE - 1) / TILE, 256>>>(h, b_self, b_neigh,
                                                       ln_gamma, ln_beta, out);
}